// round 1
// baseline (speedup 1.0000x reference)
#include <cuda_runtime.h>
#include <math_constants.h>

// Problem dims (fixed by the dataset)
#define BB 32
#define DD 256
#define TT 1024
#define KK 8192
#define NN (BB * TT)          // 32768 rows
#define ZQ_ELEMS (BB * DD * TT)  // 8388608

// Tile config for main kernel
#define NT 128     // rows per block
#define KT 128     // codebook cols per tile
#define DC 64      // D chunk
#define EPAD 68    // padded row stride (floats) for E tile, keeps 16B align, 2-way conflicts max

__device__ float  g_e2[KK];
__device__ float  g_t1[NN];
__device__ int    g_idx[NN];
__device__ double g_loss;

// ---------- packed f32x2 helpers ----------
__device__ __forceinline__ unsigned long long ffma2(unsigned long long a,
                                                    unsigned long long b,
                                                    unsigned long long c) {
    unsigned long long d;
    asm("fma.rn.f32x2 %0, %1, %2, %3;" : "=l"(d) : "l"(a), "l"(b), "l"(c));
    return d;
}
__device__ __forceinline__ unsigned long long pack_dup(float v) {
    unsigned long long p;
    asm("mov.b64 %0, {%1, %2};" : "=l"(p) : "f"(v), "f"(v));
    return p;
}
__device__ __forceinline__ void unpack2(unsigned long long p, float& lo, float& hi) {
    asm("mov.b64 {%0, %1}, %2;" : "=f"(lo), "=f"(hi) : "l"(p));
}

// ---------- kernel A: codebook norms (+ zero the loss accumulator) ----------
__global__ void prep_e2(const float* __restrict__ emb) {
    int k = blockIdx.x * 8 + (threadIdx.x >> 5);
    int lane = threadIdx.x & 31;
    const float* row = emb + (size_t)k * DD;
    float s = 0.f;
#pragma unroll
    for (int j = 0; j < 8; j++) {
        float v = row[lane + 32 * j];
        s = __fmaf_rn(v, v, s);
    }
#pragma unroll
    for (int o = 16; o > 0; o >>= 1) s += __shfl_xor_sync(0xffffffffu, s, o);
    if (lane == 0) g_e2[k] = s;
    if (blockIdx.x == 0 && threadIdx.x == 0) g_loss = 0.0;
}

// ---------- kernel B: row norms t1, SEQUENTIAL fp32 order (mimic XLA naive loop) ----------
__global__ void prep_t1(const float* __restrict__ ze) {
    int n = blockIdx.x * 256 + threadIdx.x;   // n = b*T + t; block never crosses b
    int b = n >> 10, t = n & 1023;
    const float* p = ze + ((size_t)b * DD) * TT + t;
    float acc = 0.f;
    for (int d = 0; d < DD; d++) {
        float v = p[(size_t)d * TT];
        acc = __fadd_rn(acc, __fmul_rn(v, v));   // square rounds, add rounds — no FMA
    }
    g_t1[n] = acc;
}

// ---------- kernel C: fused GEMM + argmin ----------
// grid = NN/NT = 256 blocks, 256 threads, 2 CTAs/SM -> single wave.
extern __shared__ float smem_main[];

__global__ __launch_bounds__(256, 2) void vq_main(const float* __restrict__ ze,
                                                  const float* __restrict__ emb,
                                                  float* __restrict__ out) {
    float* Xs = smem_main;                 // [DC][NT]  d-major, 32 KB
    float* Es = smem_main + DC * NT;       // [KT][EPAD] k-major, ~34 KB

    const int tid = threadIdx.x;
    const int tx = tid & 15;               // col group
    const int ty = tid >> 4;               // row group
    const int n0 = blockIdx.x * NT;
    const int b = n0 >> 10, t0 = n0 & 1023;
    const float* zeb = ze + ((size_t)b * DD) * TT + t0;

    float t1r[8];
#pragma unroll
    for (int j = 0; j < 8; j++) t1r[j] = g_t1[n0 + ty * 8 + j];

    float bestv[8];
    int bestk[8];
#pragma unroll
    for (int j = 0; j < 8; j++) { bestv[j] = CUDART_INF_F; bestk[j] = 0; }

    unsigned long long acc[4][8];

    for (int kt = 0; kt < KK; kt += KT) {
#pragma unroll
        for (int rp = 0; rp < 4; rp++)
#pragma unroll
            for (int c = 0; c < 8; c++) acc[rp][c] = 0ull;

        for (int dc = 0; dc < DD; dc += DC) {
            __syncthreads();   // protect smem from previous chunk's readers
            // load X chunk: [DC][NT], vec4, coalesced along t
#pragma unroll
            for (int i = 0; i < 8; i++) {
                int idx4 = tid + i * 256;           // < 2048
                int d = idx4 >> 5, nv = idx4 & 31;
                float4 v = *(const float4*)(zeb + (size_t)(dc + d) * TT + nv * 4);
                *(float4*)&Xs[d * NT + nv * 4] = v;
            }
            // load E chunk: [KT][DC] -> Es[k][d], vec4 along d
#pragma unroll
            for (int i = 0; i < 8; i++) {
                int idx4 = tid + i * 256;           // < 2048
                int kl = idx4 >> 4, dv = idx4 & 15;
                float4 v = *(const float4*)(emb + (size_t)(kt + kl) * DD + dc + dv * 4);
                *(float4*)&Es[kl * EPAD + dv * 4] = v;
            }
            __syncthreads();

#pragma unroll 16
            for (int d = 0; d < DC; d++) {
                unsigned long long xp[4];
#pragma unroll
                for (int rp = 0; rp < 4; rp++)
                    xp[rp] = *(const unsigned long long*)&Xs[d * NT + ty * 8 + rp * 2];
#pragma unroll
                for (int c = 0; c < 8; c++) {
                    float ev = Es[(tx + 16 * c) * EPAD + d];
                    unsigned long long ep = pack_dup(ev);
#pragma unroll
                    for (int rp = 0; rp < 4; rp++)
                        acc[rp][c] = ffma2(xp[rp], ep, acc[rp][c]);
                }
            }
        }

        // epilogue: replicate reference rounding exactly:
        // dist = fl( fl(t1 + e2) - fl(2*dot) )   (2*dot is exact; no FMA contraction)
#pragma unroll
        for (int c = 0; c < 8; c++) {
            int k = kt + tx + 16 * c;
            float e2v = g_e2[k];
#pragma unroll
            for (int rp = 0; rp < 4; rp++) {
                float lo, hi;
                unpack2(acc[rp][c], lo, hi);
                int r0 = 2 * rp, r1 = 2 * rp + 1;
                float dv0 = __fsub_rn(__fadd_rn(t1r[r0], e2v), __fmul_rn(2.0f, lo));
                float dv1 = __fsub_rn(__fadd_rn(t1r[r1], e2v), __fmul_rn(2.0f, hi));
                if (dv0 < bestv[r0] || (dv0 == bestv[r0] && k < bestk[r0])) { bestv[r0] = dv0; bestk[r0] = k; }
                if (dv1 < bestv[r1] || (dv1 == bestv[r1] && k < bestk[r1])) { bestv[r1] = dv1; bestk[r1] = k; }
            }
        }
    }

    // cross-thread argmin reduce (16 col-groups per row), reuse smem
    __syncthreads();
    float* rv = smem_main;                  // [NT][16] floats
    int* rk = (int*)(smem_main + NT * 16);  // [NT][16] ints
#pragma unroll
    for (int j = 0; j < 8; j++) {
        int r = ty * 8 + j;
        rv[r * 16 + tx] = bestv[j];
        rk[r * 16 + tx] = bestk[j];
    }
    __syncthreads();
    if (tid < NT) {
        float bv = rv[tid * 16];
        int bk = rk[tid * 16];
#pragma unroll
        for (int i = 1; i < 16; i++) {
            float v = rv[tid * 16 + i];
            int k = rk[tid * 16 + i];
            if (v < bv || (v == bv && k < bk)) { bv = v; bk = k; }
        }
        int n = n0 + tid;
        g_idx[n] = bk;
        out[ZQ_ELEMS + 1 + n] = (float)bk;   // idx output (as float)
    }
}

// ---------- kernel D: gather, straight-through output, e_loss ----------
__global__ void vq_gather(const float* __restrict__ ze, const float* __restrict__ emb,
                          float* __restrict__ out) {
    int bd = blockIdx.x;            // b*DD + d
    int b = bd >> 8, d = bd & 255;
    const float* zrow = ze + (size_t)bd * TT;
    float* orow = out + (size_t)bd * TT;
    double lsum = 0.0;
#pragma unroll
    for (int i = 0; i < 4; i++) {
        int t = threadIdx.x + i * 256;
        int k = g_idx[b * TT + t];
        float v = zrow[t];
        float e = emb[(size_t)k * DD + d];
        float diff = __fsub_rn(e, v);              // fl(z_q - z_e)
        orow[t] = __fadd_rn(v, diff);              // fl(z_e + fl(z_q - z_e))  (STE round-trip!)
        float sq = __fmul_rn(diff, diff);
        lsum += (double)sq;
    }
    __shared__ double sred[256];
    sred[threadIdx.x] = lsum;
    __syncthreads();
    for (int s = 128; s > 0; s >>= 1) {
        if (threadIdx.x < s) sred[threadIdx.x] += sred[threadIdx.x + s];
        __syncthreads();
    }
    if (threadIdx.x == 0) atomicAdd(&g_loss, sred[0]);
}

__global__ void vq_finalize(float* __restrict__ out) {
    out[ZQ_ELEMS] = (float)(g_loss / (double)ZQ_ELEMS);
}

// ---------- launch ----------
extern "C" void kernel_launch(void* const* d_in, const int* in_sizes, int n_in,
                              void* d_out, int out_size) {
    (void)in_sizes; (void)n_in; (void)out_size;
    const float* ze = (const float*)d_in[0];
    const float* emb = (const float*)d_in[1];
    float* out = (float*)d_out;

    const int smem_bytes = (DC * NT + KT * EPAD) * (int)sizeof(float);  // 67584
    cudaFuncSetAttribute(vq_main, cudaFuncAttributeMaxDynamicSharedMemorySize, smem_bytes);

    prep_e2<<<KK / 8, 256>>>(emb);
    prep_t1<<<NN / 256, 256>>>(ze);
    vq_main<<<NN / NT, 256, smem_bytes>>>(ze, emb, out);
    vq_gather<<<BB * DD, 256>>>(ze, emb, out);
    vq_finalize<<<1, 1>>>(out);
}

// round 2
// speedup vs baseline: 1.0026x; 1.0026x over previous
#include <cuda_runtime.h>
#include <math_constants.h>

// Problem dims (fixed by the dataset)
#define BB 32
#define DD 256
#define TT 1024
#define KK 8192
#define NN (BB * TT)          // 32768 rows
#define ZQ_ELEMS (BB * DD * TT)  // 8388608

// Tile config for main kernel
#define NT 128     // rows per block
#define KT 128     // codebook cols per tile
#define DC 64      // D chunk
#define EPAD 68    // padded row stride (floats) for E tile, keeps 16B align, 2-way conflicts max

__device__ float  g_e2[KK];
__device__ float  g_t1[NN];
__device__ int    g_idx[NN];
__device__ double g_loss;

// ---------- packed f32x2 helpers ----------
__device__ __forceinline__ unsigned long long ffma2(unsigned long long a,
                                                    unsigned long long b,
                                                    unsigned long long c) {
    unsigned long long d;
    asm("fma.rn.f32x2 %0, %1, %2, %3;" : "=l"(d) : "l"(a), "l"(b), "l"(c));
    return d;
}
__device__ __forceinline__ unsigned long long pack_dup(float v) {
    unsigned long long p;
    asm("mov.b64 %0, {%1, %2};" : "=l"(p) : "f"(v), "f"(v));
    return p;
}
__device__ __forceinline__ void unpack2(unsigned long long p, float& lo, float& hi) {
    asm("mov.b64 {%0, %1}, %2;" : "=f"(lo), "=f"(hi) : "l"(p));
}

// ---------- kernel A: codebook norms (+ zero the loss accumulator) ----------
__global__ void prep_e2(const float* __restrict__ emb) {
    int k = blockIdx.x * 8 + (threadIdx.x >> 5);
    int lane = threadIdx.x & 31;
    const float* row = emb + (size_t)k * DD;
    float s = 0.f;
#pragma unroll
    for (int j = 0; j < 8; j++) {
        float v = row[lane + 32 * j];
        s = __fmaf_rn(v, v, s);
    }
#pragma unroll
    for (int o = 16; o > 0; o >>= 1) s += __shfl_xor_sync(0xffffffffu, s, o);
    if (lane == 0) g_e2[k] = s;
    if (blockIdx.x == 0 && threadIdx.x == 0) g_loss = 0.0;
}

// ---------- kernel B: row norms t1, SEQUENTIAL fp32 order (mimic XLA naive loop) ----------
__global__ void prep_t1(const float* __restrict__ ze) {
    int n = blockIdx.x * 256 + threadIdx.x;   // n = b*T + t; block never crosses b
    int b = n >> 10, t = n & 1023;
    const float* p = ze + ((size_t)b * DD) * TT + t;
    float acc = 0.f;
    for (int d = 0; d < DD; d++) {
        float v = p[(size_t)d * TT];
        acc = __fadd_rn(acc, __fmul_rn(v, v));   // square rounds, add rounds — no FMA
    }
    g_t1[n] = acc;
}

// ---------- kernel C: fused GEMM + argmin ----------
// grid = NN/NT = 256 blocks, 256 threads, 2 CTAs/SM -> single wave.
extern __shared__ float smem_main[];

__global__ __launch_bounds__(256, 2) void vq_main(const float* __restrict__ ze,
                                                  const float* __restrict__ emb,
                                                  float* __restrict__ out) {
    float* Xs = smem_main;                 // [DC][NT]  d-major, 32 KB
    float* Es = smem_main + DC * NT;       // [KT][EPAD] k-major, ~34 KB

    const int tid = threadIdx.x;
    const int tx = tid & 15;               // col group
    const int ty = tid >> 4;               // row group
    const int n0 = blockIdx.x * NT;
    const int b = n0 >> 10, t0 = n0 & 1023;
    const float* zeb = ze + ((size_t)b * DD) * TT + t0;

    float t1r[8];
#pragma unroll
    for (int j = 0; j < 8; j++) t1r[j] = g_t1[n0 + ty * 8 + j];

    float bestv[8];
    int bestk[8];
#pragma unroll
    for (int j = 0; j < 8; j++) { bestv[j] = CUDART_INF_F; bestk[j] = 0; }

    unsigned long long acc[4][8];

    for (int kt = 0; kt < KK; kt += KT) {
#pragma unroll
        for (int rp = 0; rp < 4; rp++)
#pragma unroll
            for (int c = 0; c < 8; c++) acc[rp][c] = 0ull;

        for (int dc = 0; dc < DD; dc += DC) {
            __syncthreads();   // protect smem from previous chunk's readers
            // load X chunk: [DC][NT], vec4, coalesced along t
#pragma unroll
            for (int i = 0; i < 8; i++) {
                int idx4 = tid + i * 256;           // < 2048
                int d = idx4 >> 5, nv = idx4 & 31;
                float4 v = *(const float4*)(zeb + (size_t)(dc + d) * TT + nv * 4);
                *(float4*)&Xs[d * NT + nv * 4] = v;
            }
            // load E chunk: [KT][DC] -> Es[k][d], vec4 along d
#pragma unroll
            for (int i = 0; i < 8; i++) {
                int idx4 = tid + i * 256;           // < 2048
                int kl = idx4 >> 4, dv = idx4 & 15;
                float4 v = *(const float4*)(emb + (size_t)(kt + kl) * DD + dc + dv * 4);
                *(float4*)&Es[kl * EPAD + dv * 4] = v;
            }
            __syncthreads();

#pragma unroll 16
            for (int d = 0; d < DC; d++) {
                unsigned long long xp[4];
#pragma unroll
                for (int rp = 0; rp < 4; rp++)
                    xp[rp] = *(const unsigned long long*)&Xs[d * NT + ty * 8 + rp * 2];
#pragma unroll
                for (int c = 0; c < 8; c++) {
                    float ev = Es[(tx + 16 * c) * EPAD + d];
                    unsigned long long ep = pack_dup(ev);
#pragma unroll
                    for (int rp = 0; rp < 4; rp++)
                        acc[rp][c] = ffma2(xp[rp], ep, acc[rp][c]);
                }
            }
        }

        // epilogue: replicate reference rounding exactly:
        // dist = fl( fl(t1 + e2) - fl(2*dot) )   (2*dot is exact; no FMA contraction)
#pragma unroll
        for (int c = 0; c < 8; c++) {
            int k = kt + tx + 16 * c;
            float e2v = g_e2[k];
#pragma unroll
            for (int rp = 0; rp < 4; rp++) {
                float lo, hi;
                unpack2(acc[rp][c], lo, hi);
                int r0 = 2 * rp, r1 = 2 * rp + 1;
                float dv0 = __fsub_rn(__fadd_rn(t1r[r0], e2v), __fmul_rn(2.0f, lo));
                float dv1 = __fsub_rn(__fadd_rn(t1r[r1], e2v), __fmul_rn(2.0f, hi));
                if (dv0 < bestv[r0] || (dv0 == bestv[r0] && k < bestk[r0])) { bestv[r0] = dv0; bestk[r0] = k; }
                if (dv1 < bestv[r1] || (dv1 == bestv[r1] && k < bestk[r1])) { bestv[r1] = dv1; bestk[r1] = k; }
            }
        }
    }

    // cross-thread argmin reduce (16 col-groups per row), reuse smem
    __syncthreads();
    float* rv = smem_main;                  // [NT][16] floats
    int* rk = (int*)(smem_main + NT * 16);  // [NT][16] ints
#pragma unroll
    for (int j = 0; j < 8; j++) {
        int r = ty * 8 + j;
        rv[r * 16 + tx] = bestv[j];
        rk[r * 16 + tx] = bestk[j];
    }
    __syncthreads();
    if (tid < NT) {
        float bv = rv[tid * 16];
        int bk = rk[tid * 16];
#pragma unroll
        for (int i = 1; i < 16; i++) {
            float v = rv[tid * 16 + i];
            int k = rk[tid * 16 + i];
            if (v < bv || (v == bv && k < bk)) { bv = v; bk = k; }
        }
        int n = n0 + tid;
        g_idx[n] = bk;
        out[ZQ_ELEMS + 1 + n] = (float)bk;   // idx output (as float)
    }
}

// ---------- kernel D: gather, straight-through output, e_loss ----------
__global__ void vq_gather(const float* __restrict__ ze, const float* __restrict__ emb,
                          float* __restrict__ out) {
    int bd = blockIdx.x;            // b*DD + d
    int b = bd >> 8, d = bd & 255;
    const float* zrow = ze + (size_t)bd * TT;
    float* orow = out + (size_t)bd * TT;
    double lsum = 0.0;
#pragma unroll
    for (int i = 0; i < 4; i++) {
        int t = threadIdx.x + i * 256;
        int k = g_idx[b * TT + t];
        float v = zrow[t];
        float e = emb[(size_t)k * DD + d];
        float diff = __fsub_rn(e, v);              // fl(z_q - z_e)
        orow[t] = __fadd_rn(v, diff);              // fl(z_e + fl(z_q - z_e))  (STE round-trip!)
        float sq = __fmul_rn(diff, diff);
        lsum += (double)sq;
    }
    __shared__ double sred[256];
    sred[threadIdx.x] = lsum;
    __syncthreads();
    for (int s = 128; s > 0; s >>= 1) {
        if (threadIdx.x < s) sred[threadIdx.x] += sred[threadIdx.x + s];
        __syncthreads();
    }
    if (threadIdx.x == 0) atomicAdd(&g_loss, sred[0]);
}

__global__ void vq_finalize(float* __restrict__ out) {
    out[ZQ_ELEMS] = (float)(g_loss / (double)ZQ_ELEMS);
}

// ---------- launch ----------
extern "C" void kernel_launch(void* const* d_in, const int* in_sizes, int n_in,
                              void* d_out, int out_size) {
    (void)in_sizes; (void)n_in; (void)out_size;
    const float* ze = (const float*)d_in[0];
    const float* emb = (const float*)d_in[1];
    float* out = (float*)d_out;

    const int smem_bytes = (DC * NT + KT * EPAD) * (int)sizeof(float);  // 67584
    cudaFuncSetAttribute(vq_main, cudaFuncAttributeMaxDynamicSharedMemorySize, smem_bytes);

    prep_e2<<<KK / 8, 256>>>(emb);
    prep_t1<<<NN / 256, 256>>>(ze);
    vq_main<<<NN / NT, 256, smem_bytes>>>(ze, emb, out);
    vq_gather<<<BB * DD, 256>>>(ze, emb, out);
    vq_finalize<<<1, 1>>>(out);
}